// round 4
// baseline (speedup 1.0000x reference)
#include <cuda_runtime.h>
#include <cuda_bf16.h>
#include <cstdint>

#define B 384
#define D 128
#define NA 3                  // anchors per block
#define NB (B / NA)           // 128 blocks -> single wave
#define ROWF4 33              // padded row pitch in float4 (528B)
#define MARGIN 0.5f
#define NWARP (B / 32)        // 12
#define NCHUNK 4
#define CHUNK_F4 (B * D / 4 / NCHUNK)   // 3072 float4 per chunk (96 rows)
#define BARCNT 480            // 384 + 96 participants per named barrier

__device__ float g_psum[NB];
__device__ float g_pcnt[NB];
__device__ unsigned int g_ticket;   // zero-init; reset by last block

__device__ __forceinline__ void cp_async16(uint32_t dst, const void* src) {
    asm volatile("cp.async.cg.shared.global [%0], [%1], 16;" :: "r"(dst), "l"(src));
}
__device__ __forceinline__ void cp_commit() {
    asm volatile("cp.async.commit_group;" ::: "memory");
}
template <int N>
__device__ __forceinline__ void cp_wait() {
    asm volatile("cp.async.wait_group %0;" :: "n"(N) : "memory");
}
__device__ __forceinline__ void bar_arrive(int id, int cnt) {
    asm volatile("bar.arrive %0, %1;" :: "r"(id), "r"(cnt) : "memory");
}
__device__ __forceinline__ void bar_sync_named(int id, int cnt) {
    asm volatile("bar.sync %0, %1;" :: "r"(id), "r"(cnt) : "memory");
}

__global__ __launch_bounds__(B) void triplet_kernel(
    const float* __restrict__ emb,
    const int* __restrict__ labels,
    float* __restrict__ out)
{
    extern __shared__ float4 semb[];          // [B][ROWF4] staged embeddings
    __shared__ float4 sanc[NA * ROWF4];       // anchor rows
    __shared__ int   slab[B];
    __shared__ float dpos[NA][B];
    __shared__ int   npos[NA];
    __shared__ float sqa_s[NA];
    __shared__ float rsum[NWARP];
    __shared__ float rcnt[NWARP];
    __shared__ int   is_last;

    const int t  = threadIdx.x;
    const int ab = blockIdx.x * NA;
    const float4* g4 = (const float4*)emb;    // B*32 float4

    slab[t] = labels[t];
    if (t < NA) npos[t] = 0;

    const uint32_t semb_u = (uint32_t)__cvta_generic_to_shared(semb);
    const uint32_t sanc_u = (uint32_t)__cvta_generic_to_shared(sanc);

    // ---- anchors: 96 threads, one float4 each (contiguous 1.5KB) ----
    if (t < NA * (D / 4)) {
        uint32_t dst = sanc_u + (uint32_t)(((t >> 5) * ROWF4 + (t & 31)) * 16);
        cp_async16(dst, g4 + ab * (D / 4) + t);
        cp_commit();                           // group 0 (for t<96 only)
    }

    // ---- 4 chunks of 96 rows, coalesced, fire-and-forget ----
    #pragma unroll
    for (int c = 0; c < NCHUNK; c++) {
        #pragma unroll
        for (int j = 0; j < CHUNK_F4 / B; j++) {     // 8 per thread
            int g = c * CHUNK_F4 + j * B + t;
            uint32_t dst = semb_u + (uint32_t)(((g >> 5) * ROWF4 + (g & 31)) * 16);
            cp_async16(dst, g4 + g);
        }
        cp_commit();
    }

    // ---- signal per-chunk completion (release) ----
    if (t < 96) {   // 5 groups: anchor, c0..c3
        cp_wait<4>(); bar_arrive(5, BARCNT);
        cp_wait<3>(); bar_arrive(1, BARCNT);
        cp_wait<2>(); bar_arrive(2, BARCNT);
        cp_wait<1>(); bar_arrive(3, BARCNT);
        cp_wait<0>(); bar_arrive(4, BARCNT);
    } else {        // 4 groups: c0..c3
        cp_wait<3>(); bar_arrive(1, BARCNT);
        cp_wait<2>(); bar_arrive(2, BARCNT);
        cp_wait<1>(); bar_arrive(3, BARCNT);
        cp_wait<0>(); bar_arrive(4, BARCNT);
    }

    // ---- wait for anchors + own chunk only (acquire) ----
    bar_sync_named(5, BARCNT);
    const int myc = t / 96;                    // warp-uniform (96 = 3 warps)
    bar_sync_named(1 + myc, BARCNT);

    // ---- dot(row t, anchors) + |row t|^2, 2 accumulators per chain ----
    float dotA[NA], dotB[NA];
    #pragma unroll
    for (int aa = 0; aa < NA; aa++) { dotA[aa] = 0.f; dotB[aa] = 0.f; }
    float sqA = 0.f, sqB = 0.f;
    const float4* xrow = semb + t * ROWF4;

    #pragma unroll 8
    for (int k = 0; k < D / 4; k++) {
        float4 x = xrow[k];
        sqA = fmaf(x.x, x.x, fmaf(x.y, x.y, sqA));
        sqB = fmaf(x.z, x.z, fmaf(x.w, x.w, sqB));
        #pragma unroll
        for (int aa = 0; aa < NA; aa++) {
            float4 e = sanc[aa * ROWF4 + k];   // uniform -> broadcast
            dotA[aa] = fmaf(x.x, e.x, fmaf(x.y, e.y, dotA[aa]));
            dotB[aa] = fmaf(x.z, e.z, fmaf(x.w, e.w, dotB[aa]));
        }
    }
    const float sq = sqA + sqB;

    if (t >= ab && t < ab + NA) sqa_s[t - ab] = sq;
    __syncthreads();

    // ---- distances + positive gather ----
    const int lt = slab[t];
    float dist[NA];
    #pragma unroll
    for (int aa = 0; aa < NA; aa++) {
        dist[aa] = fmaxf(sqa_s[aa] - 2.f * (dotA[aa] + dotB[aa]) + sq, 0.f);
        if (lt == slab[ab + aa] && t != ab + aa) {
            int idx = atomicAdd(&npos[aa], 1);
            dpos[aa][idx] = dist[aa];
        }
    }
    __syncthreads();

    // ---- thread t as negative for each anchor ----
    float sum = 0.f, cnt = 0.f;
    #pragma unroll
    for (int aa = 0; aa < NA; aa++) {
        if (lt != slab[ab + aa]) {
            const float dn = dist[aa];
            const int np = npos[aa];
            for (int p = 0; p < np; p++) {
                float v = dpos[aa][p] - dn + MARGIN;
                if (v > 1e-16f) { sum += v; cnt += 1.f; }
            }
        }
    }

    // ---- block reduction ----
    const int lane = t & 31;
    const int warp = t >> 5;
    #pragma unroll
    for (int off = 16; off > 0; off >>= 1) {
        sum += __shfl_down_sync(0xFFFFFFFFu, sum, off);
        cnt += __shfl_down_sync(0xFFFFFFFFu, cnt, off);
    }
    if (lane == 0) { rsum[warp] = sum; rcnt[warp] = cnt; }
    __syncthreads();
    if (warp == 0) {
        float s = (lane < NWARP) ? rsum[lane] : 0.f;
        float c = (lane < NWARP) ? rcnt[lane] : 0.f;
        #pragma unroll
        for (int off = 16; off > 0; off >>= 1) {
            s += __shfl_down_sync(0xFFFFFFFFu, s, off);
            c += __shfl_down_sync(0xFFFFFFFFu, c, off);
        }
        if (lane == 0) {
            g_psum[blockIdx.x] = s;
            g_pcnt[blockIdx.x] = c;
        }
    }

    // ---- last-block final reduction ----
    __threadfence();
    if (t == 0) {
        unsigned int tk = atomicAdd(&g_ticket, 1u);
        is_last = (tk == NB - 1);
    }
    __syncthreads();

    if (is_last && warp == 0) {
        __threadfence();
        volatile float* vs = g_psum;
        volatile float* vc = g_pcnt;
        double s = 0.0, c = 0.0;
        #pragma unroll
        for (int i = lane; i < NB; i += 32) {
            s += (double)vs[i];
            c += (double)vc[i];
        }
        #pragma unroll
        for (int off = 16; off > 0; off >>= 1) {
            s += __shfl_down_sync(0xFFFFFFFFu, s, off);
            c += __shfl_down_sync(0xFFFFFFFFu, c, off);
        }
        if (lane == 0) {
            out[0] = (float)(s / (c + 1e-16));
            g_ticket = 0;                      // reset for graph replay
        }
    }
}

extern "C" void kernel_launch(void* const* d_in, const int* in_sizes, int n_in,
                              void* d_out, int out_size) {
    const float* emb    = (const float*)d_in[0];
    const int*   labels = (const int*)d_in[1];
    float*       out    = (float*)d_out;

    const size_t smem = (size_t)B * ROWF4 * sizeof(float4);   // 202,752 B dynamic
    cudaFuncSetAttribute(triplet_kernel,
                         cudaFuncAttributeMaxDynamicSharedMemorySize, (int)smem);

    triplet_kernel<<<NB, B, smem>>>(emb, labels, out);
}